// round 1
// baseline (speedup 1.0000x reference)
#include <cuda_runtime.h>
#include <cuda_bf16.h>

// Problem constants (fixed by dataset)
#define BB 64
#define NN 50000
#define EE 1600000
#define LL 20
#define BN_EPS 1e-5f

// ---------------- scratch (static device globals; no allocation) ----------------
__device__ float  g_xT[(size_t)NN * BB];     // x transposed [N, B]      12.8 MB
__device__ float  g_xhT[(size_t)NN * BB];    // x_hat transposed [N, B]  12.8 MB
__device__ int    g_counts[NN];
__device__ int    g_offsets[NN];             // exclusive scan; mutated to "ends" by scatter
__device__ int    g_csr_src[EE];
__device__ float2 g_csr_ab[EE];              // (alpha, bias) per CSR slot

// ---------------- kernels ----------------

__global__ void zero_counts_kernel() {
    int i = blockIdx.x * blockDim.x + threadIdx.x;
    if (i < NN) g_counts[i] = 0;
}

// x [B, N] -> xT [N, B], 32x32 tiles
__global__ void transpose_kernel(const float* __restrict__ x) {
    __shared__ float tile[32][33];
    int n_in = blockIdx.x * 32 + threadIdx.x;
    int b_in = blockIdx.y * 32 + threadIdx.y;
    if (n_in < NN)
        tile[threadIdx.y][threadIdx.x] = x[(size_t)b_in * NN + n_in];
    __syncthreads();
    int n_out = blockIdx.x * 32 + threadIdx.y;
    int b_out = blockIdx.y * 32 + threadIdx.x;
    if (n_out < NN)
        g_xT[(size_t)n_out * BB + b_out] = tile[threadIdx.x][threadIdx.y];
}

__global__ void init_pred_kernel(const float* __restrict__ b_lin, float* __restrict__ pred) {
    int i = blockIdx.x * blockDim.x + threadIdx.x;
    if (i < BB * LL) pred[i] = b_lin[i % LL];
}

__global__ void hist_kernel(const int* __restrict__ dst) {
    int i = blockIdx.x * blockDim.x + threadIdx.x;
    if (i < EE) atomicAdd(&g_counts[dst[i]], 1);
}

// single-block exclusive scan of g_counts -> g_offsets
__global__ void scan_kernel() {
    __shared__ int sd[1024];
    __shared__ int s_carry;
    if (threadIdx.x == 0) s_carry = 0;
    __syncthreads();
    for (int base = 0; base < NN; base += 1024) {
        int i = base + threadIdx.x;
        int v = (i < NN) ? g_counts[i] : 0;
        sd[threadIdx.x] = v;
        __syncthreads();
        #pragma unroll
        for (int off = 1; off < 1024; off <<= 1) {
            int t = (threadIdx.x >= off) ? sd[threadIdx.x - off] : 0;
            __syncthreads();
            sd[threadIdx.x] += t;
            __syncthreads();
        }
        int incl = sd[threadIdx.x];
        int carry = s_carry;
        if (i < NN) g_offsets[i] = carry + incl - v;   // exclusive
        __syncthreads();
        if (threadIdx.x == 1023) s_carry = carry + incl;
        __syncthreads();
    }
}

// bucket-scatter packed edge records; g_offsets becomes per-node "end" pointers
__global__ void scatter_kernel(const int* __restrict__ src, const int* __restrict__ dst,
                               const float* __restrict__ alpha, const float* __restrict__ bias) {
    int i = blockIdx.x * blockDim.x + threadIdx.x;
    if (i < EE) {
        int d = dst[i];
        int pos = atomicAdd(&g_offsets[d], 1);
        g_csr_src[pos] = src[i];
        g_csr_ab[pos]  = make_float2(alpha[i], bias[i]);
    }
}

__device__ __forceinline__ float warp_sum(float v) {
    #pragma unroll
    for (int m = 16; m; m >>= 1) v += __shfl_xor_sync(0xFFFFFFFFu, v, m);
    return v;
}

// one warp per node: accumulate edges, scatter-mean, tanh, BN; write x_hatT + bn
__global__ __launch_bounds__(1024) void aggregate_kernel(const float* __restrict__ gamma,
                                                         const float* __restrict__ beta,
                                                         float* __restrict__ bn_out) {
    __shared__ float sbn[64][33];
    const int warpId = threadIdx.x >> 5;
    const int lane   = threadIdx.x & 31;
    const int n0 = blockIdx.x * 32;
    const int n  = n0 + warpId;

    if (n < NN) {
        const int end = g_offsets[n];          // mutated by scatter into end pointer
        const int cnt = g_counts[n];
        int j = end - cnt;
        float2 acc = make_float2(0.f, 0.f);
        float sb = 0.f;
        const float2* __restrict__ xT2 = (const float2*)g_xT;
        for (; j < end; ++j) {
            int    s  = g_csr_src[j];
            float2 ab = g_csr_ab[j];
            float2 v  = xT2[(size_t)s * 32 + lane];
            acc.x = fmaf(ab.x, v.x, acc.x);
            acc.y = fmaf(ab.x, v.y, acc.y);
            sb += ab.y;
        }
        float invc = 1.0f / (float)(cnt > 1 ? cnt : 1);
        float2 xh = make_float2((acc.x + sb) * invc, (acc.y + sb) * invc);
        ((float2*)g_xhT)[(size_t)n * 32 + lane] = xh;

        float2 o = make_float2(tanhf(xh.x), tanhf(xh.y));
        float mu  = warp_sum(o.x + o.y) * (1.0f / 64.0f);
        float ex2 = warp_sum(o.x * o.x + o.y * o.y) * (1.0f / 64.0f);
        float var = ex2 - mu * mu;
        float rstd = rsqrtf(var + BN_EPS);
        float g  = gamma[n] * rstd;
        float be = beta[n];
        sbn[2 * lane    ][warpId] = (o.x - mu) * g + be;
        sbn[2 * lane + 1][warpId] = (o.y - mu) * g + be;
    }
    __syncthreads();
    // coalesced store of the 64x32 bn tile
    #pragma unroll
    for (int r = threadIdx.x; r < 64 * 32; r += 1024) {
        int b = r >> 5, c = r & 31;
        int nn = n0 + c;
        if (nn < NN) bn_out[(size_t)b * NN + nn] = sbn[b][c];
    }
}

// pred[b,l] += sum_n x_hatT[n,b] * W[l,n]   (chunked reduction, 128 nodes per block)
__global__ __launch_bounds__(1024) void gemm_kernel(const float* __restrict__ W,
                                                    float* __restrict__ pred) {
    __shared__ float xtile[128 * 64];   // 32 KB
    __shared__ float wtile[LL * 128];   // 10 KB
    const int n0  = blockIdx.x * 128;
    const int rem = min(128, NN - n0);
    const int tid = threadIdx.x;

    for (int idx = tid; idx < 128 * 64; idx += 1024)
        xtile[idx] = (idx < rem * 64) ? g_xhT[(size_t)n0 * 64 + idx] : 0.0f;
    for (int idx = tid; idx < LL * 128; idx += 1024) {
        int l = idx >> 7, nn = idx & 127;
        wtile[idx] = (nn < rem) ? W[(size_t)l * NN + n0 + nn] : 0.0f;
    }
    __syncthreads();

    if (tid < BB / 2 * LL) {           // 640 threads
        int l = tid % LL, b = tid / LL;
        float a0 = 0.f, a1 = 0.f;
        #pragma unroll 8
        for (int nn = 0; nn < 128; ++nn) {
            float w = wtile[l * 128 + nn];
            a0 = fmaf(xtile[nn * 64 + b],      w, a0);
            a1 = fmaf(xtile[nn * 64 + b + 32], w, a1);
        }
        atomicAdd(&pred[b * LL + l],        a0);
        atomicAdd(&pred[(b + 32) * LL + l], a1);
    }
}

// ---------------- launch ----------------
extern "C" void kernel_launch(void* const* d_in, const int* in_sizes, int n_in,
                              void* d_out, int out_size) {
    const float* x     = (const float*)d_in[0];
    const int*   eidx  = (const int*)  d_in[1];
    const float* alpha = (const float*)d_in[2];
    const float* bias  = (const float*)d_in[3];
    const float* W     = (const float*)d_in[4];
    const float* b_lin = (const float*)d_in[5];
    const float* gamma = (const float*)d_in[6];
    const float* beta  = (const float*)d_in[7];

    const int* src = eidx;
    const int* dst = eidx + EE;

    float* pred   = (float*)d_out;              // [B, L] first
    float* bn_out = (float*)d_out + BB * LL;    // then [B, N]

    zero_counts_kernel<<<(NN + 1023) / 1024, 1024>>>();
    {
        dim3 blk(32, 32), grd((NN + 31) / 32, BB / 32);
        transpose_kernel<<<grd, blk>>>(x);
    }
    init_pred_kernel<<<2, 640>>>(b_lin, pred);
    hist_kernel<<<(EE + 255) / 256, 256>>>(dst);
    scan_kernel<<<1, 1024>>>();
    scatter_kernel<<<(EE + 255) / 256, 256>>>(src, dst, alpha, bias);
    aggregate_kernel<<<(NN + 31) / 32, 1024>>>(gamma, beta, bn_out);
    gemm_kernel<<<(NN + 127) / 128, 1024>>>(W, pred);
}

// round 2
// speedup vs baseline: 1.4463x; 1.4463x over previous
#include <cuda_runtime.h>
#include <cuda_bf16.h>

// Problem constants (fixed by dataset)
#define BB 64
#define NN 50000
#define EE 1600000
#define LL 20
#define BN_EPS 1e-5f

#define SCAN_BLK 1024
#define NBLOCKS_SCAN ((NN + SCAN_BLK - 1) / SCAN_BLK)   // 49

// ---------------- scratch (static device globals; no allocation) ----------------
__device__ float  g_xT[(size_t)NN * BB];     // x transposed [N, B]      12.8 MB
__device__ float  g_xhT[(size_t)NN * BB];    // x_hat transposed [N, B]  12.8 MB
__device__ int    g_counts[NN];
__device__ float  g_bsum[NN];                // per-node sum of bias
__device__ int    g_offsets[NN];             // exclusive scan; mutated to "ends" by scatter
__device__ int    g_blocksum[NBLOCKS_SCAN];
__device__ int    g_blockoff[NBLOCKS_SCAN];
__device__ int2   g_csr[EE];                 // {src, __float_as_int(alpha)}

// ---------------- kernels ----------------

__global__ void zero_kernel() {
    int i = blockIdx.x * blockDim.x + threadIdx.x;
    if (i < NN) { g_counts[i] = 0; g_bsum[i] = 0.0f; }
}

// x [B, N] -> xT [N, B], 32x32 tiles
__global__ void transpose_kernel(const float* __restrict__ x) {
    __shared__ float tile[32][33];
    int n_in = blockIdx.x * 32 + threadIdx.x;
    int b_in = blockIdx.y * 32 + threadIdx.y;
    if (n_in < NN)
        tile[threadIdx.y][threadIdx.x] = x[(size_t)b_in * NN + n_in];
    __syncthreads();
    int n_out = blockIdx.x * 32 + threadIdx.y;
    int b_out = blockIdx.y * 32 + threadIdx.x;
    if (n_out < NN)
        g_xT[(size_t)n_out * BB + b_out] = tile[threadIdx.x][threadIdx.y];
}

__global__ void init_pred_kernel(const float* __restrict__ b_lin, float* __restrict__ pred) {
    int i = blockIdx.x * blockDim.x + threadIdx.x;
    if (i < BB * LL) pred[i] = b_lin[i % LL];
}

// histogram of dst + per-node bias sums (both batch-independent)
__global__ void hist_kernel(const int* __restrict__ dst, const float* __restrict__ bias) {
    int i = blockIdx.x * blockDim.x + threadIdx.x;
    if (i < EE) {
        int d = dst[i];
        atomicAdd(&g_counts[d], 1);
        atomicAdd(&g_bsum[d], bias[i]);
    }
}

__device__ __forceinline__ int warp_incl_scan(int v, int lane) {
    #pragma unroll
    for (int off = 1; off < 32; off <<= 1) {
        int t = __shfl_up_sync(0xFFFFFFFFu, v, off);
        if (lane >= off) v += t;
    }
    return v;
}

// phase 1: per-block exclusive scan of counts; emit block totals
__global__ __launch_bounds__(SCAN_BLK) void scan_local_kernel() {
    __shared__ int warp_tot[32];
    int i = blockIdx.x * SCAN_BLK + threadIdx.x;
    int lane = threadIdx.x & 31, wid = threadIdx.x >> 5;
    int v = (i < NN) ? g_counts[i] : 0;
    int incl = warp_incl_scan(v, lane);
    if (lane == 31) warp_tot[wid] = incl;
    __syncthreads();
    if (wid == 0) {
        int w = warp_tot[lane];
        warp_tot[lane] = warp_incl_scan(w, lane) - w;  // exclusive warp offsets
    }
    __syncthreads();
    int excl = warp_tot[wid] + incl - v;
    if (i < NN) g_offsets[i] = excl;
    if (threadIdx.x == SCAN_BLK - 1) g_blocksum[blockIdx.x] = warp_tot[wid] + incl;
}

// phase 2: scan the 49 block totals (single block, 64 threads)
__global__ void scan_blocks_kernel() {
    __shared__ int sd[64];
    int tid = threadIdx.x;
    int v = (tid < NBLOCKS_SCAN) ? g_blocksum[tid] : 0;
    sd[tid] = v;
    __syncthreads();
    #pragma unroll
    for (int off = 1; off < 64; off <<= 1) {
        int t = (tid >= off) ? sd[tid - off] : 0;
        __syncthreads();
        sd[tid] += t;
        __syncthreads();
    }
    if (tid < NBLOCKS_SCAN) g_blockoff[tid] = sd[tid] - v;
}

// phase 3: add block offsets
__global__ __launch_bounds__(SCAN_BLK) void scan_add_kernel() {
    int i = blockIdx.x * SCAN_BLK + threadIdx.x;
    if (i < NN) g_offsets[i] += g_blockoff[blockIdx.x];
}

// bucket-scatter 8-byte edge records; g_offsets becomes per-node "end" pointers
__global__ void scatter_kernel(const int* __restrict__ src, const int* __restrict__ dst,
                               const float* __restrict__ alpha) {
    int i = blockIdx.x * blockDim.x + threadIdx.x;
    if (i < EE) {
        int d = dst[i];
        int pos = atomicAdd(&g_offsets[d], 1);
        g_csr[pos] = make_int2(src[i], __float_as_int(alpha[i]));
    }
}

__device__ __forceinline__ float warp_sum(float v) {
    #pragma unroll
    for (int m = 16; m; m >>= 1) v += __shfl_xor_sync(0xFFFFFFFFu, v, m);
    return v;
}

// one warp per node: accumulate edges, scatter-mean, tanh, BN; write x_hatT + bn
__global__ __launch_bounds__(1024) void aggregate_kernel(const float* __restrict__ gamma,
                                                         const float* __restrict__ beta,
                                                         float* __restrict__ bn_out) {
    __shared__ float sbn[64][33];
    const int warpId = threadIdx.x >> 5;
    const int lane   = threadIdx.x & 31;
    const int n0 = blockIdx.x * 32;
    const int n  = n0 + warpId;

    if (n < NN) {
        const int end = g_offsets[n];          // mutated by scatter into end pointer
        const int cnt = g_counts[n];
        const int beg = end - cnt;
        float2 acc = make_float2(0.f, 0.f);
        const float2* __restrict__ xT2 = (const float2*)g_xT;
        int j = beg;
        for (; j + 2 <= end; j += 2) {
            int2 r0 = __ldg(&g_csr[j]);
            int2 r1 = __ldg(&g_csr[j + 1]);
            float2 v0 = xT2[(size_t)r0.x * 32 + lane];
            float2 v1 = xT2[(size_t)r1.x * 32 + lane];
            float a0 = __int_as_float(r0.y);
            float a1 = __int_as_float(r1.y);
            acc.x = fmaf(a0, v0.x, acc.x);
            acc.y = fmaf(a0, v0.y, acc.y);
            acc.x = fmaf(a1, v1.x, acc.x);
            acc.y = fmaf(a1, v1.y, acc.y);
        }
        if (j < end) {
            int2 r = __ldg(&g_csr[j]);
            float2 v = xT2[(size_t)r.x * 32 + lane];
            float a = __int_as_float(r.y);
            acc.x = fmaf(a, v.x, acc.x);
            acc.y = fmaf(a, v.y, acc.y);
        }
        float sb = g_bsum[n];
        float invc = 1.0f / (float)(cnt > 1 ? cnt : 1);
        float2 xh = make_float2((acc.x + sb) * invc, (acc.y + sb) * invc);
        ((float2*)g_xhT)[(size_t)n * 32 + lane] = xh;

        float2 o = make_float2(tanhf(xh.x), tanhf(xh.y));
        float mu  = warp_sum(o.x + o.y) * (1.0f / 64.0f);
        float ex2 = warp_sum(o.x * o.x + o.y * o.y) * (1.0f / 64.0f);
        float var = ex2 - mu * mu;
        float rstd = rsqrtf(var + BN_EPS);
        float g  = gamma[n] * rstd;
        float be = beta[n];
        sbn[2 * lane    ][warpId] = (o.x - mu) * g + be;
        sbn[2 * lane + 1][warpId] = (o.y - mu) * g + be;
    }
    __syncthreads();
    // coalesced store of the 64x32 bn tile
    #pragma unroll
    for (int r = threadIdx.x; r < 64 * 32; r += 1024) {
        int b = r >> 5, c = r & 31;
        int nn = n0 + c;
        if (nn < NN) bn_out[(size_t)b * NN + nn] = sbn[b][c];
    }
}

// pred[b,l] += sum_n x_hatT[n,b] * W[l,n]   (chunked reduction, 128 nodes per block)
__global__ __launch_bounds__(1024) void gemm_kernel(const float* __restrict__ W,
                                                    float* __restrict__ pred) {
    __shared__ float xtile[128 * 64];   // 32 KB
    __shared__ float wtile[LL * 128];   // 10 KB
    const int n0  = blockIdx.x * 128;
    const int rem = min(128, NN - n0);
    const int tid = threadIdx.x;

    for (int idx = tid; idx < 128 * 64; idx += 1024)
        xtile[idx] = (idx < rem * 64) ? g_xhT[(size_t)n0 * 64 + idx] : 0.0f;
    for (int idx = tid; idx < LL * 128; idx += 1024) {
        int l = idx >> 7, nn = idx & 127;
        wtile[idx] = (nn < rem) ? W[(size_t)l * NN + n0 + nn] : 0.0f;
    }
    __syncthreads();

    if (tid < BB / 2 * LL) {           // 640 threads
        int l = tid % LL, b = tid / LL;
        float a0 = 0.f, a1 = 0.f;
        #pragma unroll 8
        for (int nn = 0; nn < 128; ++nn) {
            float w = wtile[l * 128 + nn];
            a0 = fmaf(xtile[nn * 64 + b],      w, a0);
            a1 = fmaf(xtile[nn * 64 + b + 32], w, a1);
        }
        atomicAdd(&pred[b * LL + l],        a0);
        atomicAdd(&pred[(b + 32) * LL + l], a1);
    }
}

// ---------------- launch ----------------
extern "C" void kernel_launch(void* const* d_in, const int* in_sizes, int n_in,
                              void* d_out, int out_size) {
    const float* x     = (const float*)d_in[0];
    const int*   eidx  = (const int*)  d_in[1];
    const float* alpha = (const float*)d_in[2];
    const float* bias  = (const float*)d_in[3];
    const float* W     = (const float*)d_in[4];
    const float* b_lin = (const float*)d_in[5];
    const float* gamma = (const float*)d_in[6];
    const float* beta  = (const float*)d_in[7];

    const int* src = eidx;
    const int* dst = eidx + EE;

    float* pred   = (float*)d_out;              // [B, L] first
    float* bn_out = (float*)d_out + BB * LL;    // then [B, N]

    zero_kernel<<<(NN + 1023) / 1024, 1024>>>();
    {
        dim3 blk(32, 32), grd((NN + 31) / 32, BB / 32);
        transpose_kernel<<<grd, blk>>>(x);
    }
    init_pred_kernel<<<2, 640>>>(b_lin, pred);
    hist_kernel<<<(EE + 255) / 256, 256>>>(dst, bias);
    scan_local_kernel<<<NBLOCKS_SCAN, SCAN_BLK>>>();
    scan_blocks_kernel<<<1, 64>>>();
    scan_add_kernel<<<NBLOCKS_SCAN, SCAN_BLK>>>();
    scatter_kernel<<<(EE + 255) / 256, 256>>>(src, dst, alpha);
    aggregate_kernel<<<(NN + 31) / 32, 1024>>>(gamma, beta, bn_out);
    gemm_kernel<<<(NN + 127) / 128, 1024>>>(W, pred);
}